// round 3
// baseline (speedup 1.0000x reference)
#include <cuda_runtime.h>

#define NN 100000
#define EE 800000
#define HH 128
#define BB 64
#define NB1 196   // ceil(NN/512)
#define MMJ 128   // nodes per k_mm block
#define AST 132   // sAT row stride (floats)

typedef unsigned long long u64;

__device__ __forceinline__ u64 ffma2(u64 a, u64 b, u64 c) {
    u64 d;
    asm("fma.rn.f32x2 %0, %1, %2, %3;" : "=l"(d) : "l"(a), "l"(b), "l"(c));
    return d;
}
__device__ __forceinline__ u64 dupf(float x) {
    u64 d;
    asm("mov.b64 %0, {%1, %1};" : "=l"(d) : "f"(x));
    return d;
}

// ---------------- scratch (device globals: no runtime allocation) ----------------
__device__ float g_u[(size_t)NN * HH];      // node features per hop
__device__ float g_mean[(size_t)NN * HH];   // seg_mean(ea*u[col]) per node
__device__ float g_third[NN];               // seg_mean(ee) per node (per hop)
__device__ int   g_deg[NN];
__device__ int   g_start[NN + 1];
__device__ int   g_cursor[NN];
__device__ int   g_bsum[NB1 + 4];
__device__ int   g_boff[NB1 + 4];
__device__ int   g_ccol[EE];
__device__ float g_cea[EE];
__device__ float g_gs0[BB * HH], g_gs1[BB * HH];
__device__ float g_cnt[2 * BB];
__device__ float g_v0t[BB * HH], g_v1t[BB * HH];
__device__ float g_scal[BB * 10];           // s0,s1,p0,p1,a0,a1,d00,d01,d10,d11
__device__ float g_spvec[HH], g_actop[HH], g_acbot[HH];
__device__ float g_c0;

// ---------------- small utility kernels ----------------
__global__ void k_zero() {
    int i = blockIdx.x * blockDim.x + threadIdx.x;
    if (i < NN) g_deg[i] = 0;
    if (i < BB * HH) { g_gs0[i] = 0.f; g_gs1[i] = 0.f; }
    if (i < 2 * BB) { g_cnt[i] = 0.f; }
}

// precompute folded final-layer vectors
__global__ void k_prevec(const float* __restrict__ spw, const float* __restrict__ spb,
                         const float* __restrict__ acw, const float* __restrict__ acb,
                         const float* __restrict__ lastw, const float* __restrict__ lastb) {
    int t = threadIdx.x;  // 256
    if (t < HH) {
        float s = 0.f;
        for (int j = 0; j < HH; j++) s += spw[t * HH + j] * lastw[j];
        g_spvec[t] = s;
    }
    {
        float s = 0.f;
        for (int j = 0; j < HH; j++) s += acw[t * HH + j] * lastw[HH + j];
        if (t < HH) g_actop[t] = s; else g_acbot[t - HH] = s;
    }
    if (t < 32) {
        float s = 0.f;
        for (int j = t; j < HH; j += 32) s += spb[j] * lastw[j] + acb[j] * lastw[HH + j];
        for (int o = 16; o; o >>= 1) s += __shfl_down_sync(0xffffffffu, s, o);
        if (t == 0) g_c0 = s + lastb[0];
    }
}

__global__ void k_hist(const int* __restrict__ row) {
    int e = blockIdx.x * blockDim.x + threadIdx.x;
    if (e < EE) atomicAdd(&g_deg[row[e]], 1);
}

// ---- hierarchical scan ----
__global__ void k_scan1() {
    int t = threadIdx.x;                     // 256 threads, 512 nodes/block
    int n0 = blockIdx.x * 512;
    int s = 0;
    int i = n0 + t;
    if (i < NN) s += g_deg[i];
    if (i + 256 < n0 + 512 && i + 256 < NN) s += g_deg[i + 256];
    int lane = t & 31, warp = t >> 5;
    for (int o = 16; o; o >>= 1) s += __shfl_down_sync(0xffffffffu, s, o);
    __shared__ int ws[8];
    if (lane == 0) ws[warp] = s;
    __syncthreads();
    if (t == 0) {
        int tot = 0;
        #pragma unroll
        for (int w = 0; w < 8; w++) tot += ws[w];
        g_bsum[blockIdx.x] = tot;
    }
}

__global__ void k_scan2() {
    __shared__ int sh[256];
    int t = threadIdx.x;
    int v = (t < NB1) ? g_bsum[t] : 0;
    sh[t] = v;
    __syncthreads();
    for (int off = 1; off < 256; off <<= 1) {
        int u = (t >= off) ? sh[t - off] : 0;
        __syncthreads();
        sh[t] += u;
        __syncthreads();
    }
    if (t < NB1) g_boff[t] = sh[t] - v;   // exclusive
    if (t == 0) g_start[NN] = EE;
}

__global__ void k_scan3() {
    int t = threadIdx.x, blk = blockIdx.x;   // 256 threads, 2 nodes each
    int i0 = blk * 512 + t * 2;
    int d0 = (i0 < NN) ? g_deg[i0] : 0;
    int d1 = (i0 + 1 < NN) ? g_deg[i0 + 1] : 0;
    int s = d0 + d1;
    int lane = t & 31, warp = t >> 5;
    int v = s;
    for (int o = 1; o < 32; o <<= 1) {
        int u = __shfl_up_sync(0xffffffffu, v, o);
        if (lane >= o) v += u;
    }
    __shared__ int ws[8], wo[8];
    if (lane == 31) ws[warp] = v;
    __syncthreads();
    if (t == 0) {
        int run = 0;
        #pragma unroll
        for (int w = 0; w < 8; w++) { wo[w] = run; run += ws[w]; }
    }
    __syncthreads();
    int ex = v - s + wo[warp] + g_boff[blk];
    if (i0 < NN)     { g_start[i0] = ex;          g_cursor[i0] = ex; }
    if (i0 + 1 < NN) { g_start[i0 + 1] = ex + d0; g_cursor[i0 + 1] = ex + d0; }
}

__global__ void k_fill(const int* __restrict__ row, const int* __restrict__ col,
                       const float* __restrict__ ea) {
    int e = blockIdx.x * blockDim.x + threadIdx.x;
    if (e >= EE) return;
    int r = row[e];
    int idx = atomicAdd(&g_cursor[r], 1);
    g_ccol[idx] = col[e];
    g_cea[idx]  = ea[e];
}

// hop-0 third term only (u == 0 so no gather needed)
__global__ void k_third0(const float* __restrict__ l3w, const float* __restrict__ l3b) {
    int n = blockIdx.x * blockDim.x + threadIdx.x;
    if (n >= NN) return;
    float w = l3w[0], b = l3b[0];
    int s = g_start[n], e = g_start[n + 1];
    float acc = 0.f;
    for (int t = s; t < e; t++) acc += fmaxf(g_cea[t] * w + b, 0.f);
    g_third[n] = (e > s) ? acc / (float)(e - s) : 0.f;
}

// hop-0 node update
__global__ void k_node0(const float* __restrict__ x,
                        const float* __restrict__ l0w, const float* __restrict__ l0b,
                        const float* __restrict__ l1b,
                        const float* __restrict__ l2w, const float* __restrict__ l2b) {
    int i = blockIdx.x * blockDim.x + threadIdx.x;
    if (i >= NN * HH) return;
    int n = i >> 7, h = i & 127;
    float v = x[n] * l0w[h] + g_third[n] * l2w[h] + l0b[h] + l1b[h] + l2b[h];
    g_u[i] = fmaxf(v, 0.f);
}

// edge aggregation (hops 1..): warp per node, CSR gather, no atomics, 4-edge unroll.
__global__ void k_gather(const float* __restrict__ l3w, const float* __restrict__ l3b) {
    int warp = threadIdx.x >> 5, lane = threadIdx.x & 31;
    int n = blockIdx.x * 8 + warp;
    if (n >= NN) return;
    float w = l3w[0], b = l3b[0];
    int s = g_start[n], e = g_start[n + 1];
    float ax = 0.f, ay = 0.f, az = 0.f, aw = 0.f, tacc = 0.f;
    int t = s;
    for (; t + 3 < e; t += 4) {
        int c0 = g_ccol[t], c1 = g_ccol[t + 1], c2 = g_ccol[t + 2], c3 = g_ccol[t + 3];
        float a0 = g_cea[t], a1 = g_cea[t + 1], a2 = g_cea[t + 2], a3 = g_cea[t + 3];
        float4 v0 = *reinterpret_cast<const float4*>(&g_u[(size_t)c0 * HH + lane * 4]);
        float4 v1 = *reinterpret_cast<const float4*>(&g_u[(size_t)c1 * HH + lane * 4]);
        float4 v2 = *reinterpret_cast<const float4*>(&g_u[(size_t)c2 * HH + lane * 4]);
        float4 v3 = *reinterpret_cast<const float4*>(&g_u[(size_t)c3 * HH + lane * 4]);
        ax += a0 * v0.x + a1 * v1.x + a2 * v2.x + a3 * v3.x;
        ay += a0 * v0.y + a1 * v1.y + a2 * v2.y + a3 * v3.y;
        az += a0 * v0.z + a1 * v1.z + a2 * v2.z + a3 * v3.z;
        aw += a0 * v0.w + a1 * v1.w + a2 * v2.w + a3 * v3.w;
        tacc += fmaxf(a0 * w + b, 0.f) + fmaxf(a1 * w + b, 0.f)
              + fmaxf(a2 * w + b, 0.f) + fmaxf(a3 * w + b, 0.f);
    }
    for (; t < e; t++) {
        int c0 = g_ccol[t];
        float a0 = g_cea[t];
        float4 v0 = *reinterpret_cast<const float4*>(&g_u[(size_t)c0 * HH + lane * 4]);
        ax += a0 * v0.x; ay += a0 * v0.y; az += a0 * v0.z; aw += a0 * v0.w;
        tacc += fmaxf(a0 * w + b, 0.f);
    }
    float inv = (e > s) ? 1.f / (float)(e - s) : 0.f;
    float4 out = make_float4(ax * inv, ay * inv, az * inv, aw * inv);
    *reinterpret_cast<float4*>(&g_mean[(size_t)n * HH + lane * 4]) = out;
    if (lane == 0) g_third[n] = tacc * inv;
}

// node matmul + fused hop update, 8x8 micro-tile with packed f32x2 FMA.
// block: 256 threads, 128 nodes x 128 cols; W [128x128] + A^T [128xAST] in smem.
__global__ __launch_bounds__(256) void k_mm(
    const float* __restrict__ x, const float* __restrict__ W1,
    const float* __restrict__ l0w, const float* __restrict__ l2w,
    const float* __restrict__ b0, const float* __restrict__ b1,
    const float* __restrict__ b2) {
    extern __shared__ float sm[];
    float* sW  = sm;            // [128][128] row = k
    float* sAT = sm + HH * HH;  // [128][AST] row = k (transposed A)
    int tid = threadIdx.x;

    const float4* W4 = reinterpret_cast<const float4*>(W1);
    float4* sW4 = reinterpret_cast<float4*>(sW);
    #pragma unroll
    for (int i = tid; i < HH * HH / 4; i += 256) sW4[i] = W4[i];

    int n0 = blockIdx.x * MMJ;
    // coalesced gmem read; transposed smem store
    for (int i = tid; i < MMJ * HH; i += 256) {
        int h = i & 127, j = i >> 7;
        int n = n0 + j;
        float v = (n < NN) ? g_mean[(size_t)n * HH + h] : 0.f;
        sAT[h * AST + j] = v;
    }
    __syncthreads();

    int tx = tid & 15, ty = tid >> 4;
    int c0 = tx * 8, j0 = ty * 8;

    u64 acc[4][8];
    #pragma unroll
    for (int p = 0; p < 4; p++)
        #pragma unroll
        for (int c = 0; c < 8; c++) acc[p][c] = 0ULL;

    #pragma unroll 4
    for (int k = 0; k < HH; k++) {
        const u64* arow = reinterpret_cast<const u64*>(&sAT[k * AST + j0]);
        u64 ap0 = arow[0], ap1 = arow[1], ap2 = arow[2], ap3 = arow[3];
        float4 wv0 = *reinterpret_cast<const float4*>(&sW[k * HH + c0]);
        float4 wv1 = *reinterpret_cast<const float4*>(&sW[k * HH + c0 + 4]);
        u64 wd[8];
        wd[0] = dupf(wv0.x); wd[1] = dupf(wv0.y); wd[2] = dupf(wv0.z); wd[3] = dupf(wv0.w);
        wd[4] = dupf(wv1.x); wd[5] = dupf(wv1.y); wd[6] = dupf(wv1.z); wd[7] = dupf(wv1.w);
        #pragma unroll
        for (int c = 0; c < 8; c++) {
            acc[0][c] = ffma2(ap0, wd[c], acc[0][c]);
            acc[1][c] = ffma2(ap1, wd[c], acc[1][c]);
            acc[2][c] = ffma2(ap2, wd[c], acc[2][c]);
            acc[3][c] = ffma2(ap3, wd[c], acc[3][c]);
        }
    }

    float4 w0a = *reinterpret_cast<const float4*>(&l0w[c0]);
    float4 w0b = *reinterpret_cast<const float4*>(&l0w[c0 + 4]);
    float4 w2a = *reinterpret_cast<const float4*>(&l2w[c0]);
    float4 w2b = *reinterpret_cast<const float4*>(&l2w[c0 + 4]);
    float bias[8];
    {
        float4 p0 = *reinterpret_cast<const float4*>(&b0[c0]);
        float4 p1 = *reinterpret_cast<const float4*>(&b1[c0]);
        float4 p2 = *reinterpret_cast<const float4*>(&b2[c0]);
        float4 q0 = *reinterpret_cast<const float4*>(&b0[c0 + 4]);
        float4 q1 = *reinterpret_cast<const float4*>(&b1[c0 + 4]);
        float4 q2 = *reinterpret_cast<const float4*>(&b2[c0 + 4]);
        bias[0] = p0.x + p1.x + p2.x; bias[1] = p0.y + p1.y + p2.y;
        bias[2] = p0.z + p1.z + p2.z; bias[3] = p0.w + p1.w + p2.w;
        bias[4] = q0.x + q1.x + q2.x; bias[5] = q0.y + q1.y + q2.y;
        bias[6] = q0.z + q1.z + q2.z; bias[7] = q0.w + q1.w + q2.w;
    }
    float wl0[8] = {w0a.x, w0a.y, w0a.z, w0a.w, w0b.x, w0b.y, w0b.z, w0b.w};
    float wl2[8] = {w2a.x, w2a.y, w2a.z, w2a.w, w2b.x, w2b.y, w2b.z, w2b.w};

    #pragma unroll
    for (int p = 0; p < 4; p++) {
        #pragma unroll
        for (int hhalf = 0; hhalf < 2; hhalf++) {
            int n = n0 + j0 + p * 2 + hhalf;
            if (n < NN) {
                float xv = x[n], tv = g_third[n];
                float o[8];
                #pragma unroll
                for (int c = 0; c < 8; c++) {
                    float2 f2 = *reinterpret_cast<float2*>(&acc[p][c]);
                    float av = hhalf ? f2.y : f2.x;
                    o[c] = fmaxf(xv * wl0[c] + tv * wl2[c] + bias[c] + av, 0.f);
                }
                float4* dst = reinterpret_cast<float4*>(&g_u[(size_t)n * HH + c0]);
                dst[0] = make_float4(o[0], o[1], o[2], o[3]);
                dst[1] = make_float4(o[4], o[5], o[6], o[7]);
            }
        }
    }
}

// per-graph pooled sums (batch is sorted -> accumulate in registers, flush on change)
__global__ void k_pool(const float* __restrict__ x, const int* __restrict__ batch) {
    int h = threadIdx.x;               // 128
    int n0 = blockIdx.x * 512;
    if (n0 >= NN) return;
    int n1 = n0 + 512; if (n1 > NN) n1 = NN;
    int gcur = batch[n0];
    float a0 = 0.f, a1 = 0.f, c0 = 0.f, c1 = 0.f;
    for (int n = n0; n < n1; n++) {
        int g = batch[n];
        if (g != gcur) {
            atomicAdd(&g_gs0[gcur * HH + h], a0);
            atomicAdd(&g_gs1[gcur * HH + h], a1);
            if (h == 0) { atomicAdd(&g_cnt[gcur], c0); atomicAdd(&g_cnt[BB + gcur], c1); }
            a0 = a1 = c0 = c1 = 0.f;
            gcur = g;
        }
        float xv = x[n];
        float uv = g_u[(size_t)n * HH + h];
        a0 += uv * (1.f - xv); a1 += uv * xv;
        c0 += 1.f - xv;        c1 += xv;
    }
    atomicAdd(&g_gs0[gcur * HH + h], a0);
    atomicAdd(&g_gs1[gcur * HH + h], a1);
    if (h == 0) { atomicAdd(&g_cnt[gcur], c0); atomicAdd(&g_cnt[BB + gcur], c1); }
}

// per-graph: hc0/hc1, folded attention vectors v0/v1 = att_w @ hc, and 10 scalars
__global__ void k_graph(const float* __restrict__ attw, const float* __restrict__ attb) {
    __shared__ float hc0[HH], hc1[HH], v0[2 * HH], v1[2 * HH];
    int g = blockIdx.x, t = threadIdx.x;  // 256 threads
    if (t < HH) {
        float c0 = g_cnt[g], c1 = g_cnt[BB + g];
        hc0[t] = (c0 > 0.f) ? g_gs0[g * HH + t] / c0 : 0.f;
        hc1[t] = (c1 > 0.f) ? g_gs1[g * HH + t] / c1 : 0.f;
    }
    __syncthreads();
    {
        float s0 = 0.f, s1 = 0.f;
        const float* wrow = attw + t * HH;
        for (int j = 0; j < HH; j++) { float w = wrow[j]; s0 += w * hc0[j]; s1 += w * hc1[j]; }
        v0[t] = s0; v1[t] = s1;
        if (t < HH) { g_v0t[g * HH + t] = s0; g_v1t[g * HH + t] = s1; }
    }
    __syncthreads();
    int warp = t >> 5, lane = t & 31;
    for (int id = warp; id < 10; id += 8) {
        const float* vec; const float* hc;
        switch (id) {
            case 0: vec = attb;     hc = hc0; break;  // s0
            case 1: vec = attb;     hc = hc1; break;  // s1
            case 2: vec = g_spvec;  hc = hc0; break;  // p0
            case 3: vec = g_spvec;  hc = hc1; break;  // p1
            case 4: vec = g_acbot;  hc = hc0; break;  // a0
            case 5: vec = g_acbot;  hc = hc1; break;  // a1
            case 6: vec = v0 + HH;  hc = hc0; break;  // d00
            case 7: vec = v0 + HH;  hc = hc1; break;  // d01
            case 8: vec = v1 + HH;  hc = hc0; break;  // d10
            default: vec = v1 + HH; hc = hc1; break;  // d11
        }
        float s = 0.f;
        for (int j = lane; j < HH; j += 32) s += vec[j] * hc[j];
        for (int o = 16; o; o >>= 1) s += __shfl_down_sync(0xffffffffu, s, o);
        if (lane == 0) g_scal[g * 10 + id] = s;
    }
}

// per-node head: 3 dots of length 128 + softmax over 2 + folded output
__global__ void k_final(const float* __restrict__ x, const int* __restrict__ batch,
                        float* __restrict__ out) {
    int warp = threadIdx.x >> 5, lane = threadIdx.x & 31;
    int n = blockIdx.x * 8 + warp;
    if (n >= NN) return;
    int g = batch[n];
    float4 uv = *reinterpret_cast<const float4*>(&g_u[(size_t)n * HH + lane * 4]);
    float4 vA = *reinterpret_cast<const float4*>(&g_v0t[g * HH + lane * 4]);
    float4 vB = *reinterpret_cast<const float4*>(&g_v1t[g * HH + lane * 4]);
    float4 vC = *reinterpret_cast<const float4*>(&g_actop[lane * 4]);
    float da = uv.x * vA.x + uv.y * vA.y + uv.z * vA.z + uv.w * vA.w;
    float db = uv.x * vB.x + uv.y * vB.y + uv.z * vB.z + uv.w * vB.w;
    float dc = uv.x * vC.x + uv.y * vC.y + uv.z * vC.z + uv.w * vC.w;
    for (int o = 16; o; o >>= 1) {
        da += __shfl_down_sync(0xffffffffu, da, o);
        db += __shfl_down_sync(0xffffffffu, db, o);
        dc += __shfl_down_sync(0xffffffffu, dc, o);
    }
    if (lane == 0) {
        const float* sc = &g_scal[g * 10];
        bool xb = x[n] > 0.5f;
        float w0 = da + (xb ? sc[6] : sc[7]) + sc[0];
        float w1 = db + (xb ? sc[8] : sc[9]) + sc[1];
        float m = fmaxf(w0, w1);
        float e0 = __expf(w0 - m), e1 = __expf(w1 - m);
        float sw = e0 / (e0 + e1);
        out[n] = sw * sc[2] + (1.f - sw) * sc[3] + dc + (xb ? sc[4] : sc[5]) + g_c0;
    }
}

// ---------------- launch ----------------
extern "C" void kernel_launch(void* const* d_in, const int* in_sizes, int n_in,
                              void* d_out, int out_size) {
    int base = (n_in >= 21) ? 5 : 4;
    const float* x     = (const float*)d_in[0];
    const int*   ei    = (const int*)d_in[1];
    const float* ea    = (const float*)d_in[2];
    const int*   batch = (const int*)d_in[3];
    const float* l0w   = (const float*)d_in[base + 0];
    const float* l0b   = (const float*)d_in[base + 1];
    const float* l1w   = (const float*)d_in[base + 2];
    const float* l1b   = (const float*)d_in[base + 3];
    const float* l2w   = (const float*)d_in[base + 4];
    const float* l2b   = (const float*)d_in[base + 5];
    const float* l3w   = (const float*)d_in[base + 6];
    const float* l3b   = (const float*)d_in[base + 7];
    const float* attw  = (const float*)d_in[base + 8];
    const float* attb  = (const float*)d_in[base + 9];
    const float* spw   = (const float*)d_in[base + 10];
    const float* spb   = (const float*)d_in[base + 11];
    const float* acw   = (const float*)d_in[base + 12];
    const float* acb   = (const float*)d_in[base + 13];
    const float* lastw = (const float*)d_in[base + 14];
    const float* lastb = (const float*)d_in[base + 15];
    const int* row = ei;
    const int* col = ei + EE;
    float* out = (float*)d_out;

    const int SMEM_MM = (HH * HH + HH * AST) * (int)sizeof(float);  // 133120 B
    cudaFuncSetAttribute(k_mm, cudaFuncAttributeMaxDynamicSharedMemorySize, SMEM_MM);

    k_zero<<<(NN + 255) / 256, 256>>>();
    k_prevec<<<1, 256>>>(spw, spb, acw, acb, lastw, lastb);
    k_hist<<<(EE + 255) / 256, 256>>>(row);
    k_scan1<<<NB1, 256>>>();
    k_scan2<<<1, 256>>>();
    k_scan3<<<NB1, 256>>>();
    k_fill<<<(EE + 255) / 256, 256>>>(row, col, ea);

    // hop 0 (u == 0: skip gather and matmul)
    k_third0<<<(NN + 255) / 256, 256>>>(l3w + 0, l3b + 0);
    k_node0<<<(NN * HH + 255) / 256, 256>>>(x, l0w, l0b, l1b, l2w, l2b);

    // hops 1, 2
    for (int i = 1; i < 3; i++) {
        k_gather<<<(NN + 7) / 8, 256>>>(l3w + i, l3b + i);
        k_mm<<<(NN + MMJ - 1) / MMJ, 256, SMEM_MM>>>(x, l1w + i * HH * HH,
                                        l0w + i * HH, l2w + i * HH,
                                        l0b + i * HH, l1b + i * HH, l2b + i * HH);
    }

    k_pool<<<(NN + 511) / 512, 128>>>(x, batch);
    k_graph<<<BB, 256>>>(attw, attb);
    k_final<<<NN / 8, 256>>>(x, batch, out);
}

// round 4
// speedup vs baseline: 1.2158x; 1.2158x over previous
#include <cuda_runtime.h>

#define NN 100000
#define EE 800000
#define HH 128
#define BB 64
#define NB1 196   // ceil(NN/512)
#define MMJ 64    // nodes per k_mm block
#define AST 68    // sAT row stride (floats): mult of 4 (LDS.128 align), mod 32 = 4

typedef unsigned long long u64;

__device__ __forceinline__ u64 ffma2(u64 a, u64 b, u64 c) {
    u64 d;
    asm("fma.rn.f32x2 %0, %1, %2, %3;" : "=l"(d) : "l"(a), "l"(b), "l"(c));
    return d;
}
__device__ __forceinline__ u64 dupf(float x) {
    u64 d;
    asm("mov.b64 %0, {%1, %1};" : "=l"(d) : "f"(x));
    return d;
}

// ---------------- scratch (device globals: no runtime allocation) ----------------
__device__ float g_u[(size_t)NN * HH];      // node features per hop
__device__ float g_mean[(size_t)NN * HH];   // seg_mean(ea*u[col]) per node
__device__ float g_third[NN];               // seg_mean(ee) per node (per hop)
__device__ int   g_deg[NN];
__device__ int   g_start[NN + 1];
__device__ int   g_cursor[NN];
__device__ int   g_bsum[NB1 + 4];
__device__ int   g_boff[NB1 + 4];
__device__ int   g_ccol[EE];
__device__ float g_cea[EE];
__device__ float g_gs0[BB * HH], g_gs1[BB * HH];
__device__ float g_cnt[2 * BB];
__device__ float g_v0t[BB * HH], g_v1t[BB * HH];
__device__ float g_scal[BB * 10];           // s0,s1,p0,p1,a0,a1,d00,d01,d10,d11
__device__ float g_spvec[HH], g_actop[HH], g_acbot[HH];
__device__ float g_c0;

// ---------------- small utility kernels ----------------
__global__ void k_zero() {
    int i = blockIdx.x * blockDim.x + threadIdx.x;
    if (i < NN) g_deg[i] = 0;
    if (i < BB * HH) { g_gs0[i] = 0.f; g_gs1[i] = 0.f; }
    if (i < 2 * BB) { g_cnt[i] = 0.f; }
}

// precompute folded final-layer vectors
__global__ void k_prevec(const float* __restrict__ spw, const float* __restrict__ spb,
                         const float* __restrict__ acw, const float* __restrict__ acb,
                         const float* __restrict__ lastw, const float* __restrict__ lastb) {
    int t = threadIdx.x;  // 256
    if (t < HH) {
        float s = 0.f;
        for (int j = 0; j < HH; j++) s += spw[t * HH + j] * lastw[j];
        g_spvec[t] = s;
    }
    {
        float s = 0.f;
        for (int j = 0; j < HH; j++) s += acw[t * HH + j] * lastw[HH + j];
        if (t < HH) g_actop[t] = s; else g_acbot[t - HH] = s;
    }
    if (t < 32) {
        float s = 0.f;
        for (int j = t; j < HH; j += 32) s += spb[j] * lastw[j] + acb[j] * lastw[HH + j];
        for (int o = 16; o; o >>= 1) s += __shfl_down_sync(0xffffffffu, s, o);
        if (t == 0) g_c0 = s + lastb[0];
    }
}

__global__ void k_hist(const int* __restrict__ row) {
    int e = blockIdx.x * blockDim.x + threadIdx.x;
    if (e < EE) atomicAdd(&g_deg[row[e]], 1);
}

// ---- hierarchical scan ----
__global__ void k_scan1() {
    int t = threadIdx.x;                     // 256 threads, 512 nodes/block
    int n0 = blockIdx.x * 512;
    int s = 0;
    int i = n0 + t;
    if (i < NN) s += g_deg[i];
    if (i + 256 < n0 + 512 && i + 256 < NN) s += g_deg[i + 256];
    int lane = t & 31, warp = t >> 5;
    for (int o = 16; o; o >>= 1) s += __shfl_down_sync(0xffffffffu, s, o);
    __shared__ int ws[8];
    if (lane == 0) ws[warp] = s;
    __syncthreads();
    if (t == 0) {
        int tot = 0;
        #pragma unroll
        for (int w = 0; w < 8; w++) tot += ws[w];
        g_bsum[blockIdx.x] = tot;
    }
}

__global__ void k_scan2() {
    __shared__ int sh[256];
    int t = threadIdx.x;
    int v = (t < NB1) ? g_bsum[t] : 0;
    sh[t] = v;
    __syncthreads();
    for (int off = 1; off < 256; off <<= 1) {
        int u = (t >= off) ? sh[t - off] : 0;
        __syncthreads();
        sh[t] += u;
        __syncthreads();
    }
    if (t < NB1) g_boff[t] = sh[t] - v;   // exclusive
    if (t == 0) g_start[NN] = EE;
}

__global__ void k_scan3() {
    int t = threadIdx.x, blk = blockIdx.x;   // 256 threads, 2 nodes each
    int i0 = blk * 512 + t * 2;
    int d0 = (i0 < NN) ? g_deg[i0] : 0;
    int d1 = (i0 + 1 < NN) ? g_deg[i0 + 1] : 0;
    int s = d0 + d1;
    int lane = t & 31, warp = t >> 5;
    int v = s;
    for (int o = 1; o < 32; o <<= 1) {
        int u = __shfl_up_sync(0xffffffffu, v, o);
        if (lane >= o) v += u;
    }
    __shared__ int ws[8], wo[8];
    if (lane == 31) ws[warp] = v;
    __syncthreads();
    if (t == 0) {
        int run = 0;
        #pragma unroll
        for (int w = 0; w < 8; w++) { wo[w] = run; run += ws[w]; }
    }
    __syncthreads();
    int ex = v - s + wo[warp] + g_boff[blk];
    if (i0 < NN)     { g_start[i0] = ex;          g_cursor[i0] = ex; }
    if (i0 + 1 < NN) { g_start[i0 + 1] = ex + d0; g_cursor[i0 + 1] = ex + d0; }
}

__global__ void k_fill(const int* __restrict__ row, const int* __restrict__ col,
                       const float* __restrict__ ea) {
    int e = blockIdx.x * blockDim.x + threadIdx.x;
    if (e >= EE) return;
    int r = row[e];
    int idx = atomicAdd(&g_cursor[r], 1);
    g_ccol[idx] = col[e];
    g_cea[idx]  = ea[e];
}

// hop-0 third term only (u == 0 so no gather needed)
__global__ void k_third0(const float* __restrict__ l3w, const float* __restrict__ l3b) {
    int n = blockIdx.x * blockDim.x + threadIdx.x;
    if (n >= NN) return;
    float w = l3w[0], b = l3b[0];
    int s = g_start[n], e = g_start[n + 1];
    float acc = 0.f;
    for (int t = s; t < e; t++) acc += fmaxf(g_cea[t] * w + b, 0.f);
    g_third[n] = (e > s) ? acc / (float)(e - s) : 0.f;
}

// hop-0 node update
__global__ void k_node0(const float* __restrict__ x,
                        const float* __restrict__ l0w, const float* __restrict__ l0b,
                        const float* __restrict__ l1b,
                        const float* __restrict__ l2w, const float* __restrict__ l2b) {
    int i = blockIdx.x * blockDim.x + threadIdx.x;
    if (i >= NN * HH) return;
    int n = i >> 7, h = i & 127;
    float v = x[n] * l0w[h] + g_third[n] * l2w[h] + l0b[h] + l1b[h] + l2b[h];
    g_u[i] = fmaxf(v, 0.f);
}

// edge aggregation (hops 1..): warp per node, CSR gather, no atomics, 4-edge unroll.
__global__ void k_gather(const float* __restrict__ l3w, const float* __restrict__ l3b) {
    int warp = threadIdx.x >> 5, lane = threadIdx.x & 31;
    int n = blockIdx.x * 8 + warp;
    if (n >= NN) return;
    float w = l3w[0], b = l3b[0];
    int s = g_start[n], e = g_start[n + 1];
    float ax = 0.f, ay = 0.f, az = 0.f, aw = 0.f, tacc = 0.f;
    int t = s;
    for (; t + 3 < e; t += 4) {
        int c0 = g_ccol[t], c1 = g_ccol[t + 1], c2 = g_ccol[t + 2], c3 = g_ccol[t + 3];
        float a0 = g_cea[t], a1 = g_cea[t + 1], a2 = g_cea[t + 2], a3 = g_cea[t + 3];
        float4 v0 = *reinterpret_cast<const float4*>(&g_u[(size_t)c0 * HH + lane * 4]);
        float4 v1 = *reinterpret_cast<const float4*>(&g_u[(size_t)c1 * HH + lane * 4]);
        float4 v2 = *reinterpret_cast<const float4*>(&g_u[(size_t)c2 * HH + lane * 4]);
        float4 v3 = *reinterpret_cast<const float4*>(&g_u[(size_t)c3 * HH + lane * 4]);
        ax += a0 * v0.x + a1 * v1.x + a2 * v2.x + a3 * v3.x;
        ay += a0 * v0.y + a1 * v1.y + a2 * v2.y + a3 * v3.y;
        az += a0 * v0.z + a1 * v1.z + a2 * v2.z + a3 * v3.z;
        aw += a0 * v0.w + a1 * v1.w + a2 * v2.w + a3 * v3.w;
        tacc += fmaxf(a0 * w + b, 0.f) + fmaxf(a1 * w + b, 0.f)
              + fmaxf(a2 * w + b, 0.f) + fmaxf(a3 * w + b, 0.f);
    }
    for (; t < e; t++) {
        int c0 = g_ccol[t];
        float a0 = g_cea[t];
        float4 v0 = *reinterpret_cast<const float4*>(&g_u[(size_t)c0 * HH + lane * 4]);
        ax += a0 * v0.x; ay += a0 * v0.y; az += a0 * v0.z; aw += a0 * v0.w;
        tacc += fmaxf(a0 * w + b, 0.f);
    }
    float inv = (e > s) ? 1.f / (float)(e - s) : 0.f;
    float4 out = make_float4(ax * inv, ay * inv, az * inv, aw * inv);
    *reinterpret_cast<float4*>(&g_mean[(size_t)n * HH + lane * 4]) = out;
    if (lane == 0) g_third[n] = tacc * inv;
}

// node matmul + fused hop update.
// 256 threads = 8 warps; warp w owns rows j0=w*8 (8 nodes), lane owns cols c0=lane*4.
// Per k: A-row loads are warp-uniform broadcasts (2x LDS.128), W is 1 conflict-free
// LDS.128 whose u64 pairs feed fma.rn.f32x2 directly; acc packed over column pairs.
__global__ __launch_bounds__(256) void k_mm(
    const float* __restrict__ x, const float* __restrict__ W1,
    const float* __restrict__ l0w, const float* __restrict__ l2w,
    const float* __restrict__ b0, const float* __restrict__ b1,
    const float* __restrict__ b2) {
    extern __shared__ float sm[];
    float* sW  = sm;            // [128][128] row = k
    float* sAT = sm + HH * HH;  // [128][AST] row = k (transposed A)
    int tid = threadIdx.x;

    const float4* W4 = reinterpret_cast<const float4*>(W1);
    float4* sW4 = reinterpret_cast<float4*>(sW);
    #pragma unroll
    for (int i = tid; i < HH * HH / 4; i += 256) sW4[i] = W4[i];

    int n0 = blockIdx.x * MMJ;
    // coalesced gmem read; transposed smem store (4-way bank conflict, small cost)
    #pragma unroll
    for (int i = tid; i < MMJ * HH; i += 256) {
        int h = i & 127, j = i >> 7;
        int n = n0 + j;
        sAT[h * AST + j] = (n < NN) ? g_mean[(size_t)n * HH + h] : 0.f;
    }
    __syncthreads();

    int lane = tid & 31, warp = tid >> 5;
    int c0 = lane * 4, j0 = warp * 8;

    u64 acc[8][2];
    #pragma unroll
    for (int r = 0; r < 8; r++) { acc[r][0] = 0ULL; acc[r][1] = 0ULL; }

    #pragma unroll 4
    for (int k = 0; k < HH; k++) {
        float4 av0 = *reinterpret_cast<const float4*>(&sAT[k * AST + j0]);      // broadcast
        float4 av1 = *reinterpret_cast<const float4*>(&sAT[k * AST + j0 + 4]);  // broadcast
        const u64* wrow = reinterpret_cast<const u64*>(&sW[k * HH + c0]);
        u64 w0 = wrow[0], w1 = wrow[1];
        u64 ad[8];
        ad[0] = dupf(av0.x); ad[1] = dupf(av0.y); ad[2] = dupf(av0.z); ad[3] = dupf(av0.w);
        ad[4] = dupf(av1.x); ad[5] = dupf(av1.y); ad[6] = dupf(av1.z); ad[7] = dupf(av1.w);
        #pragma unroll
        for (int r = 0; r < 8; r++) {
            acc[r][0] = ffma2(ad[r], w0, acc[r][0]);
            acc[r][1] = ffma2(ad[r], w1, acc[r][1]);
        }
    }

    float4 w0v = *reinterpret_cast<const float4*>(&l0w[c0]);
    float4 w2v = *reinterpret_cast<const float4*>(&l2w[c0]);
    float4 p0 = *reinterpret_cast<const float4*>(&b0[c0]);
    float4 p1 = *reinterpret_cast<const float4*>(&b1[c0]);
    float4 p2 = *reinterpret_cast<const float4*>(&b2[c0]);
    float bias0 = p0.x + p1.x + p2.x, bias1 = p0.y + p1.y + p2.y;
    float bias2 = p0.z + p1.z + p2.z, bias3 = p0.w + p1.w + p2.w;

    #pragma unroll
    for (int r = 0; r < 8; r++) {
        int n = n0 + j0 + r;
        if (n < NN) {
            float xv = x[n], tv = g_third[n];
            float2 f0 = *reinterpret_cast<float2*>(&acc[r][0]);
            float2 f1 = *reinterpret_cast<float2*>(&acc[r][1]);
            float4 o;
            o.x = fmaxf(xv * w0v.x + tv * w2v.x + bias0 + f0.x, 0.f);
            o.y = fmaxf(xv * w0v.y + tv * w2v.y + bias1 + f0.y, 0.f);
            o.z = fmaxf(xv * w0v.z + tv * w2v.z + bias2 + f1.x, 0.f);
            o.w = fmaxf(xv * w0v.w + tv * w2v.w + bias3 + f1.y, 0.f);
            *reinterpret_cast<float4*>(&g_u[(size_t)n * HH + c0]) = o;
        }
    }
}

// per-graph pooled sums (batch is sorted -> accumulate in registers, flush on change)
__global__ void k_pool(const float* __restrict__ x, const int* __restrict__ batch) {
    int h = threadIdx.x;               // 128
    int n0 = blockIdx.x * 512;
    if (n0 >= NN) return;
    int n1 = n0 + 512; if (n1 > NN) n1 = NN;
    int gcur = batch[n0];
    float a0 = 0.f, a1 = 0.f, c0 = 0.f, c1 = 0.f;
    for (int n = n0; n < n1; n++) {
        int g = batch[n];
        if (g != gcur) {
            atomicAdd(&g_gs0[gcur * HH + h], a0);
            atomicAdd(&g_gs1[gcur * HH + h], a1);
            if (h == 0) { atomicAdd(&g_cnt[gcur], c0); atomicAdd(&g_cnt[BB + gcur], c1); }
            a0 = a1 = c0 = c1 = 0.f;
            gcur = g;
        }
        float xv = x[n];
        float uv = g_u[(size_t)n * HH + h];
        a0 += uv * (1.f - xv); a1 += uv * xv;
        c0 += 1.f - xv;        c1 += xv;
    }
    atomicAdd(&g_gs0[gcur * HH + h], a0);
    atomicAdd(&g_gs1[gcur * HH + h], a1);
    if (h == 0) { atomicAdd(&g_cnt[gcur], c0); atomicAdd(&g_cnt[BB + gcur], c1); }
}

// per-graph: hc0/hc1, folded attention vectors v0/v1 = att_w @ hc, and 10 scalars
__global__ void k_graph(const float* __restrict__ attw, const float* __restrict__ attb) {
    __shared__ float hc0[HH], hc1[HH], v0[2 * HH], v1[2 * HH];
    int g = blockIdx.x, t = threadIdx.x;  // 256 threads
    if (t < HH) {
        float c0 = g_cnt[g], c1 = g_cnt[BB + g];
        hc0[t] = (c0 > 0.f) ? g_gs0[g * HH + t] / c0 : 0.f;
        hc1[t] = (c1 > 0.f) ? g_gs1[g * HH + t] / c1 : 0.f;
    }
    __syncthreads();
    {
        float s0 = 0.f, s1 = 0.f;
        const float* wrow = attw + t * HH;
        for (int j = 0; j < HH; j++) { float w = wrow[j]; s0 += w * hc0[j]; s1 += w * hc1[j]; }
        v0[t] = s0; v1[t] = s1;
        if (t < HH) { g_v0t[g * HH + t] = s0; g_v1t[g * HH + t] = s1; }
    }
    __syncthreads();
    int warp = t >> 5, lane = t & 31;
    for (int id = warp; id < 10; id += 8) {
        const float* vec; const float* hc;
        switch (id) {
            case 0: vec = attb;     hc = hc0; break;  // s0
            case 1: vec = attb;     hc = hc1; break;  // s1
            case 2: vec = g_spvec;  hc = hc0; break;  // p0
            case 3: vec = g_spvec;  hc = hc1; break;  // p1
            case 4: vec = g_acbot;  hc = hc0; break;  // a0
            case 5: vec = g_acbot;  hc = hc1; break;  // a1
            case 6: vec = v0 + HH;  hc = hc0; break;  // d00
            case 7: vec = v0 + HH;  hc = hc1; break;  // d01
            case 8: vec = v1 + HH;  hc = hc0; break;  // d10
            default: vec = v1 + HH; hc = hc1; break;  // d11
        }
        float s = 0.f;
        for (int j = lane; j < HH; j += 32) s += vec[j] * hc[j];
        for (int o = 16; o; o >>= 1) s += __shfl_down_sync(0xffffffffu, s, o);
        if (lane == 0) g_scal[g * 10 + id] = s;
    }
}

// per-node head: 3 dots of length 128 + softmax over 2 + folded output
__global__ void k_final(const float* __restrict__ x, const int* __restrict__ batch,
                        float* __restrict__ out) {
    int warp = threadIdx.x >> 5, lane = threadIdx.x & 31;
    int n = blockIdx.x * 8 + warp;
    if (n >= NN) return;
    int g = batch[n];
    float4 uv = *reinterpret_cast<const float4*>(&g_u[(size_t)n * HH + lane * 4]);
    float4 vA = *reinterpret_cast<const float4*>(&g_v0t[g * HH + lane * 4]);
    float4 vB = *reinterpret_cast<const float4*>(&g_v1t[g * HH + lane * 4]);
    float4 vC = *reinterpret_cast<const float4*>(&g_actop[lane * 4]);
    float da = uv.x * vA.x + uv.y * vA.y + uv.z * vA.z + uv.w * vA.w;
    float db = uv.x * vB.x + uv.y * vB.y + uv.z * vB.z + uv.w * vB.w;
    float dc = uv.x * vC.x + uv.y * vC.y + uv.z * vC.z + uv.w * vC.w;
    for (int o = 16; o; o >>= 1) {
        da += __shfl_down_sync(0xffffffffu, da, o);
        db += __shfl_down_sync(0xffffffffu, db, o);
        dc += __shfl_down_sync(0xffffffffu, dc, o);
    }
    if (lane == 0) {
        const float* sc = &g_scal[g * 10];
        bool xb = x[n] > 0.5f;
        float w0 = da + (xb ? sc[6] : sc[7]) + sc[0];
        float w1 = db + (xb ? sc[8] : sc[9]) + sc[1];
        float m = fmaxf(w0, w1);
        float e0 = __expf(w0 - m), e1 = __expf(w1 - m);
        float sw = e0 / (e0 + e1);
        out[n] = sw * sc[2] + (1.f - sw) * sc[3] + dc + (xb ? sc[4] : sc[5]) + g_c0;
    }
}

// ---------------- launch ----------------
extern "C" void kernel_launch(void* const* d_in, const int* in_sizes, int n_in,
                              void* d_out, int out_size) {
    int base = (n_in >= 21) ? 5 : 4;
    const float* x     = (const float*)d_in[0];
    const int*   ei    = (const int*)d_in[1];
    const float* ea    = (const float*)d_in[2];
    const int*   batch = (const int*)d_in[3];
    const float* l0w   = (const float*)d_in[base + 0];
    const float* l0b   = (const float*)d_in[base + 1];
    const float* l1w   = (const float*)d_in[base + 2];
    const float* l1b   = (const float*)d_in[base + 3];
    const float* l2w   = (const float*)d_in[base + 4];
    const float* l2b   = (const float*)d_in[base + 5];
    const float* l3w   = (const float*)d_in[base + 6];
    const float* l3b   = (const float*)d_in[base + 7];
    const float* attw  = (const float*)d_in[base + 8];
    const float* attb  = (const float*)d_in[base + 9];
    const float* spw   = (const float*)d_in[base + 10];
    const float* spb   = (const float*)d_in[base + 11];
    const float* acw   = (const float*)d_in[base + 12];
    const float* acb   = (const float*)d_in[base + 13];
    const float* lastw = (const float*)d_in[base + 14];
    const float* lastb = (const float*)d_in[base + 15];
    const int* row = ei;
    const int* col = ei + EE;
    float* out = (float*)d_out;

    const int SMEM_MM = (HH * HH + HH * AST) * (int)sizeof(float);  // 100352 B
    cudaFuncSetAttribute(k_mm, cudaFuncAttributeMaxDynamicSharedMemorySize, SMEM_MM);

    k_zero<<<(NN + 255) / 256, 256>>>();
    k_prevec<<<1, 256>>>(spw, spb, acw, acb, lastw, lastb);
    k_hist<<<(EE + 255) / 256, 256>>>(row);
    k_scan1<<<NB1, 256>>>();
    k_scan2<<<1, 256>>>();
    k_scan3<<<NB1, 256>>>();
    k_fill<<<(EE + 255) / 256, 256>>>(row, col, ea);

    // hop 0 (u == 0: skip gather and matmul)
    k_third0<<<(NN + 255) / 256, 256>>>(l3w + 0, l3b + 0);
    k_node0<<<(NN * HH + 255) / 256, 256>>>(x, l0w, l0b, l1b, l2w, l2b);

    // hops 1, 2
    for (int i = 1; i < 3; i++) {
        k_gather<<<(NN + 7) / 8, 256>>>(l3w + i, l3b + i);
        k_mm<<<(NN + MMJ - 1) / MMJ, 256, SMEM_MM>>>(x, l1w + i * HH * HH,
                                        l0w + i * HH, l2w + i * HH,
                                        l0b + i * HH, l1b + i * HH, l2b + i * HH);
    }

    k_pool<<<(NN + 511) / 512, 128>>>(x, batch);
    k_graph<<<BB, 256>>>(attw, attb);
    k_final<<<NN / 8, 256>>>(x, batch, out);
}

// round 5
// speedup vs baseline: 1.7383x; 1.4297x over previous
#include <cuda_runtime.h>
#include <cuda_bf16.h>

#define NN 100000
#define EE 800000
#define HH 128
#define BB 64
#define NB1 196   // ceil(NN/512)
#define MMJ 64    // nodes per k_mm block
#define AST 68    // sAT row stride (floats): mult of 4 (LDS.128 align), mod 32 = 4

typedef unsigned long long u64;

__device__ __forceinline__ u64 ffma2(u64 a, u64 b, u64 c) {
    u64 d;
    asm("fma.rn.f32x2 %0, %1, %2, %3;" : "=l"(d) : "l"(a), "l"(b), "l"(c));
    return d;
}
__device__ __forceinline__ u64 dupf(float x) {
    u64 d;
    asm("mov.b64 %0, {%1, %1};" : "=l"(d) : "f"(x));
    return d;
}

// ---------------- scratch (device globals: no runtime allocation) ----------------
__device__ float g_u[(size_t)NN * HH];           // hop-2 node features (fp32, head path)
__device__ __nv_bfloat162 g_ub[(size_t)NN * 64]; // bf16 mirror of u (gather input)
__device__ float g_mean[(size_t)NN * HH];        // seg_mean(ea*u[col]) per node
__device__ float g_third[NN];                    // seg_mean(ee) per node (per hop)
__device__ int   g_deg[NN];
__device__ int   g_start[NN + 1];
__device__ int   g_cursor[NN];
__device__ int   g_bsum[NB1 + 4];
__device__ int   g_boff[NB1 + 4];
__device__ int   g_ccol[EE];
__device__ float g_cea[EE];
__device__ float g_gs0[BB * HH], g_gs1[BB * HH];
__device__ float g_cnt[2 * BB];
__device__ float g_v0t[BB * HH], g_v1t[BB * HH];
__device__ float g_scal[BB * 10];                // s0,s1,p0,p1,a0,a1,d00,d01,d10,d11
__device__ float g_spvec[HH], g_actop[HH], g_acbot[HH];
__device__ float g_c0;

// ---------------- zero + folded final-layer vectors (merged) ----------------
__global__ void k_zero(const float* __restrict__ spw, const float* __restrict__ spb,
                       const float* __restrict__ acw, const float* __restrict__ acb,
                       const float* __restrict__ lastw, const float* __restrict__ lastb) {
    int i = blockIdx.x * blockDim.x + threadIdx.x;
    if (i < NN) g_deg[i] = 0;
    if (i < BB * HH) { g_gs0[i] = 0.f; g_gs1[i] = 0.f; }
    if (i < 2 * BB) { g_cnt[i] = 0.f; }
    if (blockIdx.x == 0) {
        int t = threadIdx.x;  // 256
        if (t < HH) {
            float s = 0.f;
            for (int j = 0; j < HH; j++) s += spw[t * HH + j] * lastw[j];
            g_spvec[t] = s;
        }
        {
            float s = 0.f;
            for (int j = 0; j < HH; j++) s += acw[t * HH + j] * lastw[HH + j];
            if (t < HH) g_actop[t] = s; else g_acbot[t - HH] = s;
        }
        if (t < 32) {
            float s = 0.f;
            for (int j = t; j < HH; j += 32) s += spb[j] * lastw[j] + acb[j] * lastw[HH + j];
            for (int o = 16; o; o >>= 1) s += __shfl_down_sync(0xffffffffu, s, o);
            if (t == 0) g_c0 = s + lastb[0];
        }
    }
}

__global__ void k_hist(const int* __restrict__ row) {
    int e = blockIdx.x * blockDim.x + threadIdx.x;
    if (e < EE) atomicAdd(&g_deg[row[e]], 1);
}

// ---- hierarchical scan ----
__global__ void k_scan1() {
    int t = threadIdx.x;                     // 256 threads, 512 nodes/block
    int n0 = blockIdx.x * 512;
    int s = 0;
    int i = n0 + t;
    if (i < NN) s += g_deg[i];
    if (i + 256 < n0 + 512 && i + 256 < NN) s += g_deg[i + 256];
    int lane = t & 31, warp = t >> 5;
    for (int o = 16; o; o >>= 1) s += __shfl_down_sync(0xffffffffu, s, o);
    __shared__ int ws[8];
    if (lane == 0) ws[warp] = s;
    __syncthreads();
    if (t == 0) {
        int tot = 0;
        #pragma unroll
        for (int w = 0; w < 8; w++) tot += ws[w];
        g_bsum[blockIdx.x] = tot;
    }
}

__global__ void k_scan2() {
    __shared__ int sh[256];
    int t = threadIdx.x;
    int v = (t < NB1) ? g_bsum[t] : 0;
    sh[t] = v;
    __syncthreads();
    for (int off = 1; off < 256; off <<= 1) {
        int u = (t >= off) ? sh[t - off] : 0;
        __syncthreads();
        sh[t] += u;
        __syncthreads();
    }
    if (t < NB1) g_boff[t] = sh[t] - v;   // exclusive
    if (t == 0) g_start[NN] = EE;
}

__global__ void k_scan3() {
    int t = threadIdx.x, blk = blockIdx.x;   // 256 threads, 2 nodes each
    int i0 = blk * 512 + t * 2;
    int d0 = (i0 < NN) ? g_deg[i0] : 0;
    int d1 = (i0 + 1 < NN) ? g_deg[i0 + 1] : 0;
    int s = d0 + d1;
    int lane = t & 31, warp = t >> 5;
    int v = s;
    for (int o = 1; o < 32; o <<= 1) {
        int u = __shfl_up_sync(0xffffffffu, v, o);
        if (lane >= o) v += u;
    }
    __shared__ int ws[8], wo[8];
    if (lane == 31) ws[warp] = v;
    __syncthreads();
    if (t == 0) {
        int run = 0;
        #pragma unroll
        for (int w = 0; w < 8; w++) { wo[w] = run; run += ws[w]; }
    }
    __syncthreads();
    int ex = v - s + wo[warp] + g_boff[blk];
    if (i0 < NN)     { g_start[i0] = ex;          g_cursor[i0] = ex; }
    if (i0 + 1 < NN) { g_start[i0 + 1] = ex + d0; g_cursor[i0 + 1] = ex + d0; }
}

__global__ void k_fill(const int* __restrict__ row, const int* __restrict__ col,
                       const float* __restrict__ ea) {
    int e = blockIdx.x * blockDim.x + threadIdx.x;
    if (e >= EE) return;
    int r = row[e];
    int idx = atomicAdd(&g_cursor[r], 1);
    g_ccol[idx] = col[e];
    g_cea[idx]  = ea[e];
}

// hop-0 third term only (u == 0 so no gather needed)
__global__ void k_third0(const float* __restrict__ l3w, const float* __restrict__ l3b) {
    int n = blockIdx.x * blockDim.x + threadIdx.x;
    if (n >= NN) return;
    float w = l3w[0], b = l3b[0];
    int s = g_start[n], e = g_start[n + 1];
    float acc = 0.f;
    for (int t = s; t < e; t++) acc += fmaxf(g_cea[t] * w + b, 0.f);
    g_third[n] = (e > s) ? acc / (float)(e - s) : 0.f;
}

// hop-0 node update -> bf16 only (only consumer is hop-1 gather)
__global__ void k_node0(const float* __restrict__ x,
                        const float* __restrict__ l0w, const float* __restrict__ l0b,
                        const float* __restrict__ l1b,
                        const float* __restrict__ l2w, const float* __restrict__ l2b) {
    int i = blockIdx.x * blockDim.x + threadIdx.x;   // over NN*64 pairs
    if (i >= NN * 64) return;
    int n = i >> 6, hp = i & 63;
    int h0 = hp * 2;
    float xv = x[n], tv = g_third[n];
    float v0 = xv * l0w[h0]     + tv * l2w[h0]     + l0b[h0]     + l1b[h0]     + l2b[h0];
    float v1 = xv * l0w[h0 + 1] + tv * l2w[h0 + 1] + l0b[h0 + 1] + l1b[h0 + 1] + l2b[h0 + 1];
    g_ub[(size_t)n * 64 + hp] = __floats2bfloat162_rn(fmaxf(v0, 0.f), fmaxf(v1, 0.f));
}

// edge aggregation: warp per node, CSR gather from bf16 rows (256 B/edge), 4-edge unroll.
__global__ void k_gather(const float* __restrict__ l3w, const float* __restrict__ l3b) {
    int warp = threadIdx.x >> 5, lane = threadIdx.x & 31;
    int n = blockIdx.x * 8 + warp;
    if (n >= NN) return;
    const uint2* ub = reinterpret_cast<const uint2*>(g_ub);  // 8 B = 4 bf16 per lane
    float w = l3w[0], b = l3b[0];
    int s = g_start[n], e = g_start[n + 1];
    float ax = 0.f, ay = 0.f, az = 0.f, aw = 0.f, tacc = 0.f;
    int t = s;
    for (; t + 3 < e; t += 4) {
        int c0 = g_ccol[t], c1 = g_ccol[t + 1], c2 = g_ccol[t + 2], c3 = g_ccol[t + 3];
        float a0 = g_cea[t], a1 = g_cea[t + 1], a2 = g_cea[t + 2], a3 = g_cea[t + 3];
        uint2 r0 = ub[(size_t)c0 * 32 + lane];
        uint2 r1 = ub[(size_t)c1 * 32 + lane];
        uint2 r2 = ub[(size_t)c2 * 32 + lane];
        uint2 r3 = ub[(size_t)c3 * 32 + lane];
        float2 p0 = __bfloat1622float2(*reinterpret_cast<__nv_bfloat162*>(&r0.x));
        float2 q0 = __bfloat1622float2(*reinterpret_cast<__nv_bfloat162*>(&r0.y));
        float2 p1 = __bfloat1622float2(*reinterpret_cast<__nv_bfloat162*>(&r1.x));
        float2 q1 = __bfloat1622float2(*reinterpret_cast<__nv_bfloat162*>(&r1.y));
        float2 p2 = __bfloat1622float2(*reinterpret_cast<__nv_bfloat162*>(&r2.x));
        float2 q2 = __bfloat1622float2(*reinterpret_cast<__nv_bfloat162*>(&r2.y));
        float2 p3 = __bfloat1622float2(*reinterpret_cast<__nv_bfloat162*>(&r3.x));
        float2 q3 = __bfloat1622float2(*reinterpret_cast<__nv_bfloat162*>(&r3.y));
        ax += a0 * p0.x + a1 * p1.x + a2 * p2.x + a3 * p3.x;
        ay += a0 * p0.y + a1 * p1.y + a2 * p2.y + a3 * p3.y;
        az += a0 * q0.x + a1 * q1.x + a2 * q2.x + a3 * q3.x;
        aw += a0 * q0.y + a1 * q1.y + a2 * q2.y + a3 * q3.y;
        tacc += fmaxf(a0 * w + b, 0.f) + fmaxf(a1 * w + b, 0.f)
              + fmaxf(a2 * w + b, 0.f) + fmaxf(a3 * w + b, 0.f);
    }
    for (; t < e; t++) {
        int c0 = g_ccol[t];
        float a0 = g_cea[t];
        uint2 r0 = ub[(size_t)c0 * 32 + lane];
        float2 p0 = __bfloat1622float2(*reinterpret_cast<__nv_bfloat162*>(&r0.x));
        float2 q0 = __bfloat1622float2(*reinterpret_cast<__nv_bfloat162*>(&r0.y));
        ax += a0 * p0.x; ay += a0 * p0.y; az += a0 * q0.x; aw += a0 * q0.y;
        tacc += fmaxf(a0 * w + b, 0.f);
    }
    float inv = (e > s) ? 1.f / (float)(e - s) : 0.f;
    float4 out = make_float4(ax * inv, ay * inv, az * inv, aw * inv);
    *reinterpret_cast<float4*>(&g_mean[(size_t)n * HH + lane * 4]) = out;
    if (lane == 0) g_third[n] = tacc * inv;
}

// node matmul + fused hop update (FFMA2, warp-broadcast A).
// mode 0: emit bf16 only (intermediate hop); mode 1: emit fp32 only (last hop).
__global__ __launch_bounds__(256) void k_mm(
    const float* __restrict__ x, const float* __restrict__ W1,
    const float* __restrict__ l0w, const float* __restrict__ l2w,
    const float* __restrict__ b0, const float* __restrict__ b1,
    const float* __restrict__ b2, int mode) {
    extern __shared__ float sm[];
    float* sW  = sm;            // [128][128] row = k
    float* sAT = sm + HH * HH;  // [128][AST] row = k (transposed A)
    int tid = threadIdx.x;

    const float4* W4 = reinterpret_cast<const float4*>(W1);
    float4* sW4 = reinterpret_cast<float4*>(sW);
    #pragma unroll
    for (int i = tid; i < HH * HH / 4; i += 256) sW4[i] = W4[i];

    int n0 = blockIdx.x * MMJ;
    #pragma unroll
    for (int i = tid; i < MMJ * HH; i += 256) {
        int h = i & 127, j = i >> 7;
        int n = n0 + j;
        sAT[h * AST + j] = (n < NN) ? g_mean[(size_t)n * HH + h] : 0.f;
    }
    __syncthreads();

    int lane = tid & 31, warp = tid >> 5;
    int c0 = lane * 4, j0 = warp * 8;

    u64 acc[8][2];
    #pragma unroll
    for (int r = 0; r < 8; r++) { acc[r][0] = 0ULL; acc[r][1] = 0ULL; }

    #pragma unroll 4
    for (int k = 0; k < HH; k++) {
        float4 av0 = *reinterpret_cast<const float4*>(&sAT[k * AST + j0]);      // broadcast
        float4 av1 = *reinterpret_cast<const float4*>(&sAT[k * AST + j0 + 4]);  // broadcast
        const u64* wrow = reinterpret_cast<const u64*>(&sW[k * HH + c0]);
        u64 w0 = wrow[0], w1 = wrow[1];
        u64 ad[8];
        ad[0] = dupf(av0.x); ad[1] = dupf(av0.y); ad[2] = dupf(av0.z); ad[3] = dupf(av0.w);
        ad[4] = dupf(av1.x); ad[5] = dupf(av1.y); ad[6] = dupf(av1.z); ad[7] = dupf(av1.w);
        #pragma unroll
        for (int r = 0; r < 8; r++) {
            acc[r][0] = ffma2(ad[r], w0, acc[r][0]);
            acc[r][1] = ffma2(ad[r], w1, acc[r][1]);
        }
    }

    float4 w0v = *reinterpret_cast<const float4*>(&l0w[c0]);
    float4 w2v = *reinterpret_cast<const float4*>(&l2w[c0]);
    float4 p0 = *reinterpret_cast<const float4*>(&b0[c0]);
    float4 p1 = *reinterpret_cast<const float4*>(&b1[c0]);
    float4 p2 = *reinterpret_cast<const float4*>(&b2[c0]);
    float bias0 = p0.x + p1.x + p2.x, bias1 = p0.y + p1.y + p2.y;
    float bias2 = p0.z + p1.z + p2.z, bias3 = p0.w + p1.w + p2.w;

    uint2* ub = reinterpret_cast<uint2*>(g_ub);
    #pragma unroll
    for (int r = 0; r < 8; r++) {
        int n = n0 + j0 + r;
        if (n < NN) {
            float xv = x[n], tv = g_third[n];
            float2 f0 = *reinterpret_cast<float2*>(&acc[r][0]);
            float2 f1 = *reinterpret_cast<float2*>(&acc[r][1]);
            float4 o;
            o.x = fmaxf(xv * w0v.x + tv * w2v.x + bias0 + f0.x, 0.f);
            o.y = fmaxf(xv * w0v.y + tv * w2v.y + bias1 + f0.y, 0.f);
            o.z = fmaxf(xv * w0v.z + tv * w2v.z + bias2 + f1.x, 0.f);
            o.w = fmaxf(xv * w0v.w + tv * w2v.w + bias3 + f1.y, 0.f);
            if (mode == 0) {
                __nv_bfloat162 lo = __floats2bfloat162_rn(o.x, o.y);
                __nv_bfloat162 hi = __floats2bfloat162_rn(o.z, o.w);
                uint2 pk;
                pk.x = *reinterpret_cast<unsigned*>(&lo);
                pk.y = *reinterpret_cast<unsigned*>(&hi);
                ub[(size_t)n * 32 + lane] = pk;
            } else {
                *reinterpret_cast<float4*>(&g_u[(size_t)n * HH + c0]) = o;
            }
        }
    }
}

// per-graph pooled sums (batch sorted -> register accumulate, flush on change)
__global__ void k_pool(const float* __restrict__ x, const int* __restrict__ batch) {
    int h = threadIdx.x;               // 128
    int n0 = blockIdx.x * 128;
    if (n0 >= NN) return;
    int n1 = n0 + 128; if (n1 > NN) n1 = NN;
    int gcur = batch[n0];
    float a0 = 0.f, a1 = 0.f, c0 = 0.f, c1 = 0.f;
    for (int n = n0; n < n1; n++) {
        int g = batch[n];
        if (g != gcur) {
            atomicAdd(&g_gs0[gcur * HH + h], a0);
            atomicAdd(&g_gs1[gcur * HH + h], a1);
            if (h == 0) { atomicAdd(&g_cnt[gcur], c0); atomicAdd(&g_cnt[BB + gcur], c1); }
            a0 = a1 = c0 = c1 = 0.f;
            gcur = g;
        }
        float xv = x[n];
        float uv = g_u[(size_t)n * HH + h];
        a0 += uv * (1.f - xv); a1 += uv * xv;
        c0 += 1.f - xv;        c1 += xv;
    }
    atomicAdd(&g_gs0[gcur * HH + h], a0);
    atomicAdd(&g_gs1[gcur * HH + h], a1);
    if (h == 0) { atomicAdd(&g_cnt[gcur], c0); atomicAdd(&g_cnt[BB + gcur], c1); }
}

// per-graph: hc0/hc1, folded attention vectors v0/v1 = att_w @ hc, and 10 scalars
__global__ void k_graph(const float* __restrict__ attw, const float* __restrict__ attb) {
    __shared__ float hc0[HH], hc1[HH], v0[2 * HH], v1[2 * HH];
    int g = blockIdx.x, t = threadIdx.x;  // 256 threads
    if (t < HH) {
        float c0 = g_cnt[g], c1 = g_cnt[BB + g];
        hc0[t] = (c0 > 0.f) ? g_gs0[g * HH + t] / c0 : 0.f;
        hc1[t] = (c1 > 0.f) ? g_gs1[g * HH + t] / c1 : 0.f;
    }
    __syncthreads();
    {
        float s0 = 0.f, s1 = 0.f;
        const float* wrow = attw + t * HH;
        for (int j = 0; j < HH; j++) { float w = wrow[j]; s0 += w * hc0[j]; s1 += w * hc1[j]; }
        v0[t] = s0; v1[t] = s1;
        if (t < HH) { g_v0t[g * HH + t] = s0; g_v1t[g * HH + t] = s1; }
    }
    __syncthreads();
    int warp = t >> 5, lane = t & 31;
    for (int id = warp; id < 10; id += 8) {
        const float* vec; const float* hc;
        switch (id) {
            case 0: vec = attb;     hc = hc0; break;  // s0
            case 1: vec = attb;     hc = hc1; break;  // s1
            case 2: vec = g_spvec;  hc = hc0; break;  // p0
            case 3: vec = g_spvec;  hc = hc1; break;  // p1
            case 4: vec = g_acbot;  hc = hc0; break;  // a0
            case 5: vec = g_acbot;  hc = hc1; break;  // a1
            case 6: vec = v0 + HH;  hc = hc0; break;  // d00
            case 7: vec = v0 + HH;  hc = hc1; break;  // d01
            case 8: vec = v1 + HH;  hc = hc0; break;  // d10
            default: vec = v1 + HH; hc = hc1; break;  // d11
        }
        float s = 0.f;
        for (int j = lane; j < HH; j += 32) s += vec[j] * hc[j];
        for (int o = 16; o; o >>= 1) s += __shfl_down_sync(0xffffffffu, s, o);
        if (lane == 0) g_scal[g * 10 + id] = s;
    }
}

// per-node head: 3 dots of length 128 + softmax over 2 + folded output
__global__ void k_final(const float* __restrict__ x, const int* __restrict__ batch,
                        float* __restrict__ out) {
    int warp = threadIdx.x >> 5, lane = threadIdx.x & 31;
    int n = blockIdx.x * 8 + warp;
    if (n >= NN) return;
    int g = batch[n];
    float4 uv = *reinterpret_cast<const float4*>(&g_u[(size_t)n * HH + lane * 4]);
    float4 vA = *reinterpret_cast<const float4*>(&g_v0t[g * HH + lane * 4]);
    float4 vB = *reinterpret_cast<const float4*>(&g_v1t[g * HH + lane * 4]);
    float4 vC = *reinterpret_cast<const float4*>(&g_actop[lane * 4]);
    float da = uv.x * vA.x + uv.y * vA.y + uv.z * vA.z + uv.w * vA.w;
    float db = uv.x * vB.x + uv.y * vB.y + uv.z * vB.z + uv.w * vB.w;
    float dc = uv.x * vC.x + uv.y * vC.y + uv.z * vC.z + uv.w * vC.w;
    for (int o = 16; o; o >>= 1) {
        da += __shfl_down_sync(0xffffffffu, da, o);
        db += __shfl_down_sync(0xffffffffu, db, o);
        dc += __shfl_down_sync(0xffffffffu, dc, o);
    }
    if (lane == 0) {
        const float* sc = &g_scal[g * 10];
        bool xb = x[n] > 0.5f;
        float w0 = da + (xb ? sc[6] : sc[7]) + sc[0];
        float w1 = db + (xb ? sc[8] : sc[9]) + sc[1];
        float m = fmaxf(w0, w1);
        float e0 = __expf(w0 - m), e1 = __expf(w1 - m);
        float sw = e0 / (e0 + e1);
        out[n] = sw * sc[2] + (1.f - sw) * sc[3] + dc + (xb ? sc[4] : sc[5]) + g_c0;
    }
}

// ---------------- launch ----------------
extern "C" void kernel_launch(void* const* d_in, const int* in_sizes, int n_in,
                              void* d_out, int out_size) {
    int base = (n_in >= 21) ? 5 : 4;
    const float* x     = (const float*)d_in[0];
    const int*   ei    = (const int*)d_in[1];
    const float* ea    = (const float*)d_in[2];
    const int*   batch = (const int*)d_in[3];
    const float* l0w   = (const float*)d_in[base + 0];
    const float* l0b   = (const float*)d_in[base + 1];
    const float* l1w   = (const float*)d_in[base + 2];
    const float* l1b   = (const float*)d_in[base + 3];
    const float* l2w   = (const float*)d_in[base + 4];
    const float* l2b   = (const float*)d_in[base + 5];
    const float* l3w   = (const float*)d_in[base + 6];
    const float* l3b   = (const float*)d_in[base + 7];
    const float* attw  = (const float*)d_in[base + 8];
    const float* attb  = (const float*)d_in[base + 9];
    const float* spw   = (const float*)d_in[base + 10];
    const float* spb   = (const float*)d_in[base + 11];
    const float* acw   = (const float*)d_in[base + 12];
    const float* acb   = (const float*)d_in[base + 13];
    const float* lastw = (const float*)d_in[base + 14];
    const float* lastb = (const float*)d_in[base + 15];
    const int* row = ei;
    const int* col = ei + EE;
    float* out = (float*)d_out;

    const int SMEM_MM = (HH * HH + HH * AST) * (int)sizeof(float);  // 100352 B
    cudaFuncSetAttribute(k_mm, cudaFuncAttributeMaxDynamicSharedMemorySize, SMEM_MM);

    k_zero<<<(NN + 255) / 256, 256>>>(spw, spb, acw, acb, lastw, lastb);
    k_hist<<<(EE + 255) / 256, 256>>>(row);
    k_scan1<<<NB1, 256>>>();
    k_scan2<<<1, 256>>>();
    k_scan3<<<NB1, 256>>>();
    k_fill<<<(EE + 255) / 256, 256>>>(row, col, ea);

    // hop 0 (u == 0: skip gather and matmul); emits bf16 u only
    k_third0<<<(NN + 255) / 256, 256>>>(l3w + 0, l3b + 0);
    k_node0<<<(NN * 64 + 255) / 256, 256>>>(x, l0w, l0b, l1b, l2w, l2b);

    // hop 1 (bf16 out), hop 2 (fp32 out)
    for (int i = 1; i < 3; i++) {
        k_gather<<<(NN + 7) / 8, 256>>>(l3w + i, l3b + i);
        k_mm<<<(NN + MMJ - 1) / MMJ, 256, SMEM_MM>>>(x, l1w + i * HH * HH,
                                        l0w + i * HH, l2w + i * HH,
                                        l0b + i * HH, l1b + i * HH, l2b + i * HH,
                                        (i == 2) ? 1 : 0);
    }

    k_pool<<<(NN + 127) / 128, 128>>>(x, batch);
    k_graph<<<BB, 256>>>(attw, attb);
    k_final<<<NN / 8, 256>>>(x, batch, out);
}